// round 3
// baseline (speedup 1.0000x reference)
#include <cuda_runtime.h>
#include <cstdint>

#define NB 128   // batch
#define NC 16    // c rows
#define NF 128   // f cols
#define ND 512   // feature dim
#define DK 32    // GEMM k-chunk
#define NEG_INF __int_as_float(0xff800000)

// Scratch (no cudaMalloc allowed): xn stored transposed per m: [m][d][c]
__device__ float g_xnT[NB * ND * NC];     // 4 MB
__device__ float g_fnorm[NB * NF];        // 64 KB

// ---------------------------------------------------------------------------
// Kernel 1: normalize c_feats (store d-major transposed) + f row norms
// blocks [0, 2048): one c-row each; blocks [2048, 18432): one f-row each
// ---------------------------------------------------------------------------
__global__ void __launch_bounds__(128) prep_kernel(
    const float* __restrict__ c_feats, const float* __restrict__ f_feats)
{
    const int b   = blockIdx.x;
    const int tid = threadIdx.x;
    const bool is_c = (b < NB * NC);
    const float* row = is_c ? (c_feats + (size_t)b * ND)
                            : (f_feats + (size_t)(b - NB * NC) * ND);
    float4 x = ((const float4*)row)[tid];   // 128 threads * 4 = 512
    float ss = x.x * x.x + x.y * x.y + x.z * x.z + x.w * x.w;
    #pragma unroll
    for (int o = 16; o; o >>= 1) ss += __shfl_xor_sync(0xffffffffu, ss, o);
    __shared__ float wr[4];
    if ((tid & 31) == 0) wr[tid >> 5] = ss;
    __syncthreads();
    float nrm = sqrtf(wr[0] + wr[1] + wr[2] + wr[3]);

    if (is_c) {
        int m = b >> 4, c = b & 15;
        float* dst = g_xnT + (size_t)m * (ND * NC) + c;
        int d0 = tid * 4;
        dst[(size_t)(d0 + 0) * NC] = x.x / nrm;
        dst[(size_t)(d0 + 1) * NC] = x.y / nrm;
        dst[(size_t)(d0 + 2) * NC] = x.z / nrm;
        dst[(size_t)(d0 + 3) * NC] = x.w / nrm;
    } else {
        if (tid == 0) g_fnorm[b - NB * NC] = nrm;
    }
}

// ---------------------------------------------------------------------------
// Kernel 2: per-pair GEMM + DTW + backtrack + mask store.
// One CTA per (m,n) pair, 128 threads = one per f column.
//
// SMEM (floats):
//   xs  [0, 8192)            : x tile, [512][16] d-major (broadcast reads)
//   fsT [8192, 8192+4128)    : f chunk transposed [32][129] (pad -> no conflicts)
//   --- reused after GEMM ---
//   Dm  [0, 2193)            : DP table [17][129]
//   Cb  [2208, 2336)         : cumsum exchange
//   wrs [2336, 2344)         : warp partials (4 sum + 4 max)
//   mask[8192, 10240)        : [16][128] path mask
// ---------------------------------------------------------------------------
#define SMEM_FLOATS (8192 + 32 * 129)
#define SMEM_BYTES  (SMEM_FLOATS * 4)

__device__ __forceinline__ void fma2(unsigned long long& d,
                                     unsigned long long a,
                                     unsigned long long b) {
    asm("fma.rn.f32x2 %0, %1, %2, %0;" : "+l"(d) : "l"(a), "l"(b));
}

__global__ void __launch_bounds__(128, 4) dtw_kernel(
    const float* __restrict__ f_feats, float* __restrict__ out)
{
    extern __shared__ float smem[];
    float* xs   = smem;            // 8192
    float* fsT  = smem + 8192;     // 32*129
    float* Dm   = smem;            // reuse of xs
    float* Cb   = smem + 2208;
    float* wrs  = smem + 2336;     // [0..3] sum partials
    float* wrm  = smem + 2340;     // [0..3] max partials
    float* mask = smem + 8192;     // reuse of fsT

    const int pair = blockIdx.x;
    const int m = pair & 127;      // m fastest -> concurrent CTAs share f[n]
    const int n = pair >> 7;
    const int tid  = threadIdx.x;
    const int lane = tid & 31;
    const int wid  = tid >> 5;

    // ---- load normalized X tile (contiguous: g_xnT already [d][c]) ----
    {
        const float4* xg  = (const float4*)(g_xnT + (size_t)m * (ND * NC));
        float4*       xd4 = (float4*)xs;
        #pragma unroll
        for (int w = 0; w < 16; w++) xd4[tid + w * 128] = xg[tid + w * 128];
    }

    // ---- GEMM: acc[c pairs] for this thread's f-column (f = tid) ----
    unsigned long long acc[8];
    #pragma unroll
    for (int q = 0; q < 8; q++) acc[q] = 0ull;

    const float* fbase = f_feats + (size_t)n * (NF * ND);

    for (int k0 = 0; k0 < ND; k0 += DK) {
        __syncthreads();   // fsT free (also covers xs ready on first iter)
        // load f chunk [128 rows][32 cols] -> fsT transposed [32][129]
        #pragma unroll
        for (int it = 0; it < 8; it++) {
            int q   = tid + it * 128;
            int row = q >> 3;
            int c4  = q & 7;
            float4 v = *(const float4*)(fbase + (size_t)row * ND + k0 + c4 * 4);
            int d = c4 * 4;
            fsT[(d + 0) * 129 + row] = v.x;
            fsT[(d + 1) * 129 + row] = v.y;
            fsT[(d + 2) * 129 + row] = v.z;
            fsT[(d + 3) * 129 + row] = v.w;
        }
        __syncthreads();
        #pragma unroll
        for (int d = 0; d < DK; d++) {
            float fv = fsT[d * 129 + tid];
            unsigned long long bb;
            asm("mov.b64 %0, {%1, %1};" : "=l"(bb) : "f"(fv));
            const ulonglong2* xr = (const ulonglong2*)(xs + (k0 + d) * NC);
            #pragma unroll
            for (int q = 0; q < 4; q++) {
                ulonglong2 xv = xr[q];
                fma2(acc[2 * q + 0], xv.x, bb);   // c = 4q, 4q+1
                fma2(acc[2 * q + 1], xv.y, bb);   // c = 4q+2, 4q+3
            }
        }
    }
    __syncthreads();

    const float fnrm = g_fnorm[n * NF + tid];

    // ---- init DP row 0 and zero the mask ----
    Dm[tid + 1] = NEG_INF;
    if (tid == 0) Dm[0] = 0.0f;
    #pragma unroll
    for (int w = 0; w < 16; w++) mask[tid + w * 128] = 0.0f;
    __syncthreads();

    // ---- DP rows: D[i,j] = Ccum[j] + cummax_k<=j(A[k] - Ccum[k-1]) ----
    for (int i = 1; i <= NC; i++) {
        const int c = i - 1;
        unsigned long long av = acc[c >> 1];
        float s = (c & 1) ? __uint_as_float((unsigned)(av >> 32))
                          : __uint_as_float((unsigned)(av & 0xffffffffu));
        if (tid <= c) s = s / fnrm;   // tri region uses normalized similarity

        const float* Pv = Dm + (size_t)(i - 1) * 129;
        float A = fmaxf(Pv[tid], Pv[tid + 1]);   // max(diag, up)

        // inclusive block cumsum of s
        float cs = s;
        #pragma unroll
        for (int o = 1; o < 32; o <<= 1) {
            float t = __shfl_up_sync(0xffffffffu, cs, o);
            if (lane >= o) cs += t;
        }
        if (lane == 31) wrs[wid] = cs;
        __syncthreads();
        float pre = 0.0f;
        if (wid > 0) pre += wrs[0];
        if (wid > 1) pre += wrs[1];
        if (wid > 2) pre += wrs[2];
        float Ccum = pre + cs;
        Cb[tid] = Ccum;
        __syncthreads();
        float Cm1 = (tid == 0) ? 0.0f : Cb[tid - 1];
        float T = A - Cm1;

        // inclusive block cummax of T (exact)
        float mx = T;
        #pragma unroll
        for (int o = 1; o < 32; o <<= 1) {
            float t = __shfl_up_sync(0xffffffffu, mx, o);
            if (lane >= o) mx = fmaxf(mx, t);
        }
        if (lane == 31) wrm[wid] = mx;
        __syncthreads();
        if (wid > 0) mx = fmaxf(mx, wrm[0]);
        if (wid > 1) mx = fmaxf(mx, wrm[1]);
        if (wid > 2) mx = fmaxf(mx, wrm[2]);

        Dm[i * 129 + tid + 1] = Ccum + mx;
        if (tid == 0) Dm[i * 129] = NEG_INF;
        __syncthreads();
    }

    // ---- backtrack (argmax first-max: up > left > diag), serial thread ----
    if (tid == 0) {
        int i = NC, j = NF;
        #pragma unroll 1
        for (int step = 0; step < NC + NF && (i > 0 && j > 0); step++) {
            mask[(i - 1) * NF + (j - 1)] = 1.0f;
            float up = Dm[(i - 1) * 129 + j];
            float lf = Dm[i * 129 + (j - 1)];
            float dg = Dm[(i - 1) * 129 + (j - 1)];
            int mv;
            if (up >= lf && up >= dg) mv = 0;
            else if (lf >= dg)        mv = 1;
            else                      mv = 2;
            if (mv != 1) i--;
            if (mv != 0) j--;
        }
    }
    __syncthreads();

    // ---- store mask [16][128] coalesced ----
    {
        float4*       og  = (float4*)(out + (size_t)(m * NB + n) * (NC * NF));
        const float4* ms4 = (const float4*)mask;
        #pragma unroll
        for (int w = 0; w < 4; w++) og[tid + w * 128] = ms4[tid + w * 128];
    }
}

// ---------------------------------------------------------------------------
extern "C" void kernel_launch(void* const* d_in, const int* in_sizes, int n_in,
                              void* d_out, int out_size)
{
    const float* c_feats = (const float*)d_in[0];
    const float* f_feats = (const float*)d_in[1];
    float* out = (float*)d_out;

    // 49280 B > 48 KB default dynamic-smem opt-in (idempotent, capture-safe:
    // not a stream-ordered op)
    cudaFuncSetAttribute(dtw_kernel,
                         cudaFuncAttributeMaxDynamicSharedMemorySize,
                         SMEM_BYTES);

    prep_kernel<<<NB * NC + NB * NF, 128>>>(c_feats, f_feats);
    dtw_kernel<<<NB * NB, 128, SMEM_BYTES>>>(f_feats, out);
}